// round 6
// baseline (speedup 1.0000x reference)
#include <cuda_runtime.h>
#include <cuda_bf16.h>
#include <cuda_fp8.h>
#include <math.h>
#include <stdint.h>

#define BATCH 64
#define TT    2048
#define ENC   512
#define UNITS 512
#define VOCAB 32
#define TCH   8

// ---- device scratch (no allocations allowed) ----
__device__ float g_hidden[BATCH * UNITS];
__device__ float g_scoreP[BATCH * 2 * TT];
__device__ float g_w[BATCH * TT];
__device__ float g_ctxP[BATCH * TCH * ENC];
__device__ float g_gxP[8 * BATCH * 3 * UNITS];
__device__ float g_ghP[8 * BATCH * 3 * UNITS];
__device__ float g_hidP[8 * BATCH * UNITS];
__device__ __align__(16) uint8_t g_H8[(size_t)BATCH * TT * ENC];   // H in e4m3
__device__ __align__(16) uint8_t g_W1T8[UNITS * ENC];              // fp8(W1^T * 64) [n][k]

#define W1_SCALE     64.0f
#define W1_INV_SCALE 0.015625f

// =====================================================================
// helpers
// =====================================================================
__device__ __forceinline__ uint32_t smem_u32(const void* p) {
    uint32_t a;
    asm("{ .reg .u64 t; cvta.to.shared.u64 t, %1; cvt.u32.u64 %0, t; }"
        : "=r"(a) : "l"(p));
    return a;
}
#define CP16(dst, src) asm volatile( \
    "cp.async.cg.shared.global [%0], [%1], 16;\n" :: "r"(dst), "l"(src))
#define CP_COMMIT() asm volatile("cp.async.commit_group;\n")
#define CP_WAIT1()  asm volatile("cp.async.wait_group 1;\n")
#define CP_WAIT0()  asm volatile("cp.async.wait_group 0;\n")
#define LDSM4(R0, R1, R2, R3, A) asm volatile( \
    "ldmatrix.sync.aligned.m8n8.x4.shared.b16 {%0,%1,%2,%3}, [%4];" \
    : "=r"(R0), "=r"(R1), "=r"(R2), "=r"(R3) : "r"(A))

__device__ __forceinline__ void mma_fp8(float* c, const uint32_t* a, const uint32_t* b) {
    asm volatile(
        "mma.sync.aligned.m16n8k32.row.col.f32.e4m3.e4m3.f32 "
        "{%0,%1,%2,%3}, {%4,%5,%6,%7}, {%8,%9}, {%0,%1,%2,%3};\n"
        : "+f"(c[0]), "+f"(c[1]), "+f"(c[2]), "+f"(c[3])
        : "r"(a[0]), "r"(a[1]), "r"(a[2]), "r"(a[3]), "r"(b[0]), "r"(b[1]));
}
__device__ __forceinline__ float tanh_fast(float x) {
    float r;
    asm("tanh.approx.f32 %0, %1;" : "=f"(r) : "f"(x));
    return r;
}
__device__ __forceinline__ unsigned short f2_to_e4m3x2(float lo, float hi) {
    float2 v = make_float2(lo, hi);
    return (unsigned short)__nv_cvt_float2_to_fp8x2(v, __NV_SATFINITE, __NV_E4M3);
}

// =====================================================================
// K0a: H fp32 -> e4m3 (16 elems/thread)
// =====================================================================
__global__ void convH8_kernel(const float* __restrict__ H) {
    size_t i = ((size_t)blockIdx.x * 256 + threadIdx.x) * 16;
    float4 a = *(const float4*)(H + i);
    float4 b = *(const float4*)(H + i + 4);
    float4 c = *(const float4*)(H + i + 8);
    float4 d = *(const float4*)(H + i + 12);
    union { unsigned short h[8]; uint4 u; } o;
    o.h[0] = f2_to_e4m3x2(a.x, a.y);
    o.h[1] = f2_to_e4m3x2(a.z, a.w);
    o.h[2] = f2_to_e4m3x2(b.x, b.y);
    o.h[3] = f2_to_e4m3x2(b.z, b.w);
    o.h[4] = f2_to_e4m3x2(c.x, c.y);
    o.h[5] = f2_to_e4m3x2(c.z, c.w);
    o.h[6] = f2_to_e4m3x2(d.x, d.y);
    o.h[7] = f2_to_e4m3x2(d.z, d.w);
    *(uint4*)(g_H8 + i) = o.u;
}

// K0b: W1 [k][n] fp32 -> g_W1T8 [n][k] = e4m3(W1^T * 64)
__global__ void convW18_kernel(const float* __restrict__ W1) {
    __shared__ float t[32][33];
    int bx = blockIdx.x * 32, by = blockIdx.y * 32;
    t[threadIdx.y][threadIdx.x] = W1[(by + threadIdx.y) * UNITS + bx + threadIdx.x];
    __syncthreads();
    float v = t[threadIdx.x][threadIdx.y] * W1_SCALE;
    g_W1T8[(size_t)(bx + threadIdx.y) * ENC + by + threadIdx.x] =
        (uint8_t)__nv_cvt_float_to_fp8(v, __NV_SATFINITE, __NV_E4M3);
}

// =====================================================================
// K1: batched small GEMM partial: outP[kz][b][c] = In[b, kz*64:+64] @ W[., c]
// =====================================================================
__global__ void gemm64_kernel(const float* __restrict__ In,
                              const float* __restrict__ W, int ldW,
                              float* __restrict__ outP) {
    const int c0 = blockIdx.x * 128;
    const int kz = blockIdx.y;
    const int tid = threadIdx.x, tc = tid & 127, bh = tid >> 7;
    __shared__ float xs[64][8];
    __shared__ float Ws[8][128];
    float acc[32];
    #pragma unroll
    for (int i = 0; i < 32; i++) acc[i] = 0.f;

    const int kbeg = kz * 64;
    for (int k0 = kbeg; k0 < kbeg + 64; k0 += 8) {
        #pragma unroll
        for (int j = 0; j < 2; j++) {
            int e = tid + j * 256;
            xs[e >> 3][e & 7] = In[(e >> 3) * UNITS + k0 + (e & 7)];
        }
        #pragma unroll
        for (int j = 0; j < 4; j++) {
            int e = tid + j * 256;
            Ws[e >> 7][e & 127] = W[(size_t)(k0 + (e >> 7)) * ldW + c0 + (e & 127)];
        }
        __syncthreads();
        #pragma unroll
        for (int kk = 0; kk < 8; kk++) {
            float wv = Ws[kk][tc];
            #pragma unroll
            for (int bb = 0; bb < 32; bb++) acc[bb] += xs[bh * 32 + bb][kk] * wv;
        }
        __syncthreads();
    }
    #pragma unroll
    for (int bb = 0; bb < 32; bb++)
        outP[((size_t)kz * BATCH + bh * 32 + bb) * ldW + c0 + tc] = acc[bb];
}

__global__ void hidden_combine_kernel(const float* __restrict__ W2b) {
    int b = blockIdx.x, u = threadIdx.x;
    float a = W2b[u];
    #pragma unroll
    for (int p = 0; p < 8; p++) a += g_hidP[((size_t)p * BATCH + b) * UNITS + u];
    g_hidden[b * UNITS + u] = a;
}

// =====================================================================
// K2: fp8 mma.sync + ldmatrix score GEMM. Block 128(T) x 256(N), K chunk 128.
//   scoreP[b,ny,t] = sum_{n in half} V[n]*tanh(H@W1 + W1b[n] + hidden[b,n])
// 128-byte rows (128 fp8), SW128 swizzle, double-buffered cp.async.
// k32-e4m3 fragments are byte-identical to k16-bf16 with unit = fp8 pair,
// so ldmatrix addressing matches the validated bf16 kernel exactly.
// =====================================================================
#define SM_A(buf) ((uint32_t)(buf) * 16384u)
#define SM_B(buf) (32768u + (uint32_t)(buf) * 32768u)
#define SMEM_SCORE_BYTES 102400

__global__ void __launch_bounds__(256, 1)
score_kernel(const float* __restrict__ W1b, const float* __restrict__ Vw) {
    extern __shared__ uint32_t dyn[];
    float* sbias = (float*)(dyn + 24576);   // 256 f
    float* sV    = sbias + 256;             // 256 f
    float* red   = sV + 256;                // 512 f

    const int tid = threadIdx.x;
    const int w = tid >> 5, lane = tid & 31;
    const int g = lane >> 2, tig = lane & 3;
    const int warpM = w & 1, warpN = w >> 1;
    const int b = blockIdx.z, t0 = blockIdx.x * 128, n0 = blockIdx.y * 256;
    const uint32_t sbase = smem_u32(dyn);

    sbias[tid] = W1b[n0 + tid] + g_hidden[b * UNITS + n0 + tid];
    sV[tid]    = Vw[n0 + tid];

    const uint8_t* Ag = g_H8   + ((size_t)b * TT + t0) * ENC;
    const uint8_t* Bg = g_W1T8 + (size_t)n0 * ENC;

    auto load_chunk = [&](int buf, int k0) {
        #pragma unroll
        for (int j = 0; j < 4; j++) {               // A: 128 rows x 8 x 16B segs
            int e = tid + j * 256, r = e >> 3, s = e & 7;
            uint32_t off = SM_A(buf) + (uint32_t)r * 128u
                         + (uint32_t)((s ^ (r & 7)) << 4);
            CP16(sbase + off, Ag + (size_t)r * ENC + k0 + s * 16);
        }
        #pragma unroll
        for (int j = 0; j < 8; j++) {               // B: 256 rows x 8 x 16B segs
            int e = tid + j * 256, r = e >> 3, s = e & 7;
            uint32_t off = SM_B(buf) + (uint32_t)r * 128u
                         + (uint32_t)((s ^ (r & 7)) << 4);
            CP16(sbase + off, Bg + (size_t)r * ENC + k0 + s * 16);
        }
    };

    // ldmatrix per-thread row offsets (b16-unit view: 64 units per 128B row)
    uint32_t aOff[4], aRs[4], bOff[4], bRs[4];
    const uint32_t aHi = (lane >> 4) & 1;
    const uint32_t bHi = (lane >> 3) & 1;
    #pragma unroll
    for (int mt = 0; mt < 4; mt++) {
        int row = warpM * 64 + mt * 16 + (lane & 15);
        aOff[mt] = (uint32_t)row * 128u;
        aRs[mt]  = (uint32_t)(row & 7);
    }
    #pragma unroll
    for (int pr = 0; pr < 4; pr++) {
        int n = warpN * 64 + pr * 16 + (lane & 7) + ((lane >> 4) << 3);
        bOff[pr] = (uint32_t)n * 128u;
        bRs[pr]  = (uint32_t)(n & 7);
    }

    float acc[4][8][4];
    #pragma unroll
    for (int mt = 0; mt < 4; mt++)
        #pragma unroll
        for (int nt = 0; nt < 8; nt++)
            #pragma unroll
            for (int q = 0; q < 4; q++) acc[mt][nt][q] = 0.f;

    load_chunk(0, 0);
    CP_COMMIT();

    const int NS = ENC / 128;   // 4 stages of k128
    for (int s = 0; s < NS; s++) {
        if (s < NS - 1) {
            load_chunk((s + 1) & 1, (s + 1) * 128);
            CP_COMMIT();
            CP_WAIT1();
        } else {
            CP_WAIT0();
        }
        __syncthreads();
        const int cur = s & 1;

        #pragma unroll
        for (int kk = 0; kk < 4; kk++) {    // kk covers k32 fp8 = 32 bytes
            uint32_t af[4][4], bq[4][4];
            #pragma unroll
            for (int mt = 0; mt < 4; mt++) {
                uint32_t addr = sbase + SM_A(cur) + aOff[mt]
                              + (((((uint32_t)kk << 1) | aHi) ^ aRs[mt]) << 4);
                LDSM4(af[mt][0], af[mt][1], af[mt][2], af[mt][3], addr);
            }
            #pragma unroll
            for (int pr = 0; pr < 4; pr++) {
                uint32_t addr = sbase + SM_B(cur) + bOff[pr]
                              + (((((uint32_t)kk << 1) | bHi) ^ bRs[pr]) << 4);
                LDSM4(bq[pr][0], bq[pr][1], bq[pr][2], bq[pr][3], addr);
            }
            #pragma unroll
            for (int mt = 0; mt < 4; mt++)
                #pragma unroll
                for (int pr = 0; pr < 4; pr++) {
                    mma_fp8(acc[mt][pr * 2],     af[mt], &bq[pr][0]);
                    mma_fp8(acc[mt][pr * 2 + 1], af[mt], &bq[pr][2]);
                }
        }
        __syncthreads();
    }

    // epilogue: unscale, bias+hidden, tanh, dot V, reduce over n
    float pa[4], pb[4];
    #pragma unroll
    for (int mt = 0; mt < 4; mt++) { pa[mt] = 0.f; pb[mt] = 0.f; }
    #pragma unroll
    for (int nt = 0; nt < 8; nt++) {
        int nn = warpN * 64 + nt * 8 + 2 * tig;
        float s0 = sbias[nn], s1 = sbias[nn + 1];
        float v0 = sV[nn],    v1 = sV[nn + 1];
        #pragma unroll
        for (int mt = 0; mt < 4; mt++) {
            pa[mt] += v0 * tanh_fast(acc[mt][nt][0] * W1_INV_SCALE + s0)
                    + v1 * tanh_fast(acc[mt][nt][1] * W1_INV_SCALE + s1);
            pb[mt] += v0 * tanh_fast(acc[mt][nt][2] * W1_INV_SCALE + s0)
                    + v1 * tanh_fast(acc[mt][nt][3] * W1_INV_SCALE + s1);
        }
    }
    #pragma unroll
    for (int mt = 0; mt < 4; mt++) {
        pa[mt] += __shfl_xor_sync(0xffffffffu, pa[mt], 1);
        pa[mt] += __shfl_xor_sync(0xffffffffu, pa[mt], 2);
        pb[mt] += __shfl_xor_sync(0xffffffffu, pb[mt], 1);
        pb[mt] += __shfl_xor_sync(0xffffffffu, pb[mt], 2);
    }
    if (tig == 0) {
        #pragma unroll
        for (int mt = 0; mt < 4; mt++) {
            int r = warpM * 64 + mt * 16 + g;
            red[warpN * 128 + r]     = pa[mt];
            red[warpN * 128 + r + 8] = pb[mt];
        }
    }
    __syncthreads();
    if (tid < 128) {
        float s = red[tid] + red[128 + tid] + red[256 + tid] + red[384 + tid];
        g_scoreP[((size_t)b * 2 + blockIdx.y) * TT + t0 + tid] = s;
    }
}

// =====================================================================
// K3: softmax over T per batch
// =====================================================================
__global__ void softmax_kernel() {
    int b = blockIdx.x, tid = threadIdx.x;
    __shared__ float red[256];
    float sv[8];
    float mx = -1e30f;
    #pragma unroll
    for (int i = 0; i < 8; i++) {
        int t = tid + i * 256;
        sv[i] = g_scoreP[(size_t)b * 2 * TT + t] + g_scoreP[((size_t)b * 2 + 1) * TT + t];
        mx = fmaxf(mx, sv[i]);
    }
    red[tid] = mx; __syncthreads();
    for (int o = 128; o > 0; o >>= 1) {
        if (tid < o) red[tid] = fmaxf(red[tid], red[tid + o]);
        __syncthreads();
    }
    mx = red[0]; __syncthreads();
    float sum = 0.f;
    #pragma unroll
    for (int i = 0; i < 8; i++) { sv[i] = expf(sv[i] - mx); sum += sv[i]; }
    red[tid] = sum; __syncthreads();
    for (int o = 128; o > 0; o >>= 1) {
        if (tid < o) red[tid] += red[tid + o];
        __syncthreads();
    }
    float inv = 1.f / red[0];
    #pragma unroll
    for (int i = 0; i < 8; i++) g_w[b * TT + tid + i * 256] = sv[i] * inv;
}

// =====================================================================
// K4: context partials from fp32 H (float2 vectorized)
// =====================================================================
__global__ void context_kernel(const float* __restrict__ H) {
    int b = blockIdx.y, ch = blockIdx.x, tid = threadIdx.x;   // 256 threads
    const int TC = TT / TCH;
    __shared__ float ws[TC];
    int tBeg = ch * TC;
    for (int i = tid; i < TC; i += 256) ws[i] = g_w[b * TT + tBeg + i];
    __syncthreads();
    float ax = 0.f, ay = 0.f;
    const float2* Hb = (const float2*)(H + ((size_t)b * TT + tBeg) * ENC) + tid;
    #pragma unroll 4
    for (int t = 0; t < TC; t++) {
        float2 v = Hb[(size_t)t * (ENC / 2)];
        ax += ws[t] * v.x;
        ay += ws[t] * v.y;
    }
    float* dst = g_ctxP + ((size_t)b * TCH + ch) * ENC + 2 * tid;
    dst[0] = ax; dst[1] = ay;
}

// =====================================================================
// K5: GRU combine (Keras reset_after=True, gate order z,r,h)
// =====================================================================
__global__ void gru_combine_kernel(const float* __restrict__ s0,
                                   const float* __restrict__ bi,
                                   const float* __restrict__ br,
                                   float* __restrict__ s_out) {
    int b = blockIdx.x, u = threadIdx.x;
    float xz = bi[u], xr = bi[UNITS + u], xh = bi[2 * UNITS + u];
    float hz = br[u], hr = br[UNITS + u], hh = br[2 * UNITS + u];
    #pragma unroll
    for (int p = 0; p < 8; p++) {
        const float* X  = g_gxP + ((size_t)p * BATCH + b) * (3 * UNITS);
        const float* Hg = g_ghP + ((size_t)p * BATCH + b) * (3 * UNITS);
        xz += X[u];  xr += X[UNITS + u];  xh += X[2 * UNITS + u];
        hz += Hg[u]; hr += Hg[UNITS + u]; hh += Hg[2 * UNITS + u];
    }
    float hprev = s0[b * UNITS + u];
    float z  = 1.f / (1.f + expf(-(xz + hz)));
    float r  = 1.f / (1.f + expf(-(xr + hr)));
    float hc = tanhf(xh + r * hh);
    s_out[b * UNITS + u] = z * hprev + (1.f - z) * hc;
}

// =====================================================================
// K6: gated fusion + vocab projection
// =====================================================================
__global__ void fusion_kernel(const float* __restrict__ Wfa, const float* __restrict__ Wfab,
                              const float* __restrict__ Wff, const float* __restrict__ Wffb,
                              const float* __restrict__ Wfh, const float* __restrict__ Wfhb,
                              const float* __restrict__ Wy,  const float* __restrict__ Wyb,
                              const float* __restrict__ s_t, float* __restrict__ y_out) {
    __shared__ float ctx[ENC], pc[UNITS], st[UNITS], ft[UNITS], yred[512];
    int b = blockIdx.x, u = threadIdx.x;

    float c = 0.f;
    #pragma unroll
    for (int ch = 0; ch < TCH; ch++) c += g_ctxP[((size_t)b * TCH + ch) * ENC + u];
    ctx[u] = c;
    st[u]  = s_t[b * UNITS + u];
    __syncthreads();

    float p = Wfab[u];
    #pragma unroll 4
    for (int k = 0; k < ENC; k++) p += ctx[k] * Wfa[(size_t)k * UNITS + u];
    pc[u] = p;
    __syncthreads();

    float fw = Wffb[u] + Wfhb[u];
    #pragma unroll 4
    for (int k = 0; k < UNITS; k++)
        fw += pc[k] * Wff[(size_t)k * UNITS + u] + st[k] * Wfh[(size_t)k * UNITS + u];
    fw = 1.f / (1.f + expf(-fw));
    ft[u] = pc[u] * fw + st[u];
    __syncthreads();

    int v = u & 31, part = u >> 5;
    float acc = 0.f;
    for (int k = part; k < UNITS; k += 16) acc += ft[k] * Wy[(size_t)k * VOCAB + v];
    yred[u] = acc;
    __syncthreads();
    if (part == 0) {
        float s = Wyb[v];
        #pragma unroll
        for (int pp = 0; pp < 16; pp++) s += yred[pp * 32 + v];
        y_out[b * VOCAB + v] = s;
    }
}

// =====================================================================
extern "C" void kernel_launch(void* const* d_in, const int* in_sizes, int n_in,
                              void* d_out, int out_size) {
    const float* h_t   = (const float*)d_in[0];
    const float* s_t_m = (const float*)d_in[1];
    const float* H     = (const float*)d_in[2];
    const float* s0    = (const float*)d_in[3];
    const float* W1w   = (const float*)d_in[4];
    const float* W1b   = (const float*)d_in[5];
    const float* W2w   = (const float*)d_in[6];
    const float* W2b   = (const float*)d_in[7];
    const float* Vw    = (const float*)d_in[8];
    // d_in[9] = V_b: constant over t, cancels in softmax
    const float* gWx   = (const float*)d_in[10];
    const float* gWh   = (const float*)d_in[11];
    const float* gbi   = (const float*)d_in[12];
    const float* gbr   = (const float*)d_in[13];
    const float* Wfa   = (const float*)d_in[14];
    const float* Wfab  = (const float*)d_in[15];
    const float* Wff   = (const float*)d_in[16];
    const float* Wffb  = (const float*)d_in[17];
    const float* Wfh   = (const float*)d_in[18];
    const float* Wfhb  = (const float*)d_in[19];
    const float* Wy    = (const float*)d_in[20];
    const float* Wyb   = (const float*)d_in[21];

    float* out   = (float*)d_out;
    float* y_out = out;                       // y_t: [64, 32]
    float* s_out = out + BATCH * VOCAB;       // s_t: [64, 512]

    float* d_gx  = nullptr; cudaGetSymbolAddress((void**)&d_gx,  g_gxP);
    float* d_gh  = nullptr; cudaGetSymbolAddress((void**)&d_gh,  g_ghP);
    float* d_hid = nullptr; cudaGetSymbolAddress((void**)&d_hid, g_hidP);

    cudaFuncSetAttribute(score_kernel,
                         cudaFuncAttributeMaxDynamicSharedMemorySize, SMEM_SCORE_BYTES);

    convH8_kernel<<<16384, 256>>>(H);
    convW18_kernel<<<dim3(16, 16), dim3(32, 32)>>>(W1w);
    gemm64_kernel<<<dim3(4, 8), 256>>>(s_t_m, W2w, UNITS, d_hid);
    hidden_combine_kernel<<<BATCH, UNITS>>>(W2b);
    gemm64_kernel<<<dim3(12, 8), 256>>>(h_t, gWx, 3 * UNITS, d_gx);
    gemm64_kernel<<<dim3(12, 8), 256>>>(s0, gWh, 3 * UNITS, d_gh);
    score_kernel<<<dim3(TT / 128, 2, BATCH), 256, SMEM_SCORE_BYTES>>>(W1b, Vw);
    gru_combine_kernel<<<BATCH, UNITS>>>(s0, gbi, gbr, s_out);
    softmax_kernel<<<BATCH, 256>>>();
    context_kernel<<<dim3(TCH, BATCH), 256>>>(H);
    fusion_kernel<<<BATCH, UNITS>>>(Wfa, Wfab, Wff, Wffb, Wfh, Wfhb, Wy, Wyb,
                                    s_out, y_out);
}

// round 7
// speedup vs baseline: 1.1957x; 1.1957x over previous
#include <cuda_runtime.h>
#include <cuda_bf16.h>
#include <math.h>
#include <stdint.h>

#define BATCH 64
#define TT    2048
#define ENC   512
#define UNITS 512
#define VOCAB 32
#define TCH   8

// ---- device scratch (no allocations allowed) ----
__device__ float g_scoreP[BATCH * 2 * TT];
__device__ float g_w[BATCH * TT];
__device__ float g_ctxP[BATCH * TCH * ENC];
__device__ float g_gxP[8 * BATCH * 3 * UNITS];
__device__ float g_ghP[8 * BATCH * 3 * UNITS];
__device__ float g_hidP[8 * BATCH * UNITS];
__device__ __align__(16) __nv_bfloat16 g_W1Tb[UNITS * ENC];   // W1^T bf16 [n][k]

// =====================================================================
// helpers
// =====================================================================
__device__ __forceinline__ uint32_t smem_u32(const void* p) {
    uint32_t a;
    asm("{ .reg .u64 t; cvta.to.shared.u64 t, %1; cvt.u32.u64 %0, t; }"
        : "=r"(a) : "l"(p));
    return a;
}
#define CP16(dst, src) asm volatile( \
    "cp.async.cg.shared.global [%0], [%1], 16;\n" :: "r"(dst), "l"(src))
#define CP_COMMIT() asm volatile("cp.async.commit_group;\n")
#define CP_WAIT1()  asm volatile("cp.async.wait_group 1;\n")
#define CP_WAIT0()  asm volatile("cp.async.wait_group 0;\n")
#define LDSM4(R0, R1, R2, R3, A) asm volatile( \
    "ldmatrix.sync.aligned.m8n8.x4.shared.b16 {%0,%1,%2,%3}, [%4];" \
    : "=r"(R0), "=r"(R1), "=r"(R2), "=r"(R3) : "r"(A))

__device__ __forceinline__ void mma_bf16(float* c, const uint32_t* a, const uint32_t* b) {
    asm volatile(
        "mma.sync.aligned.m16n8k16.row.col.f32.bf16.bf16.f32 "
        "{%0,%1,%2,%3}, {%4,%5,%6,%7}, {%8,%9}, {%0,%1,%2,%3};\n"
        : "+f"(c[0]), "+f"(c[1]), "+f"(c[2]), "+f"(c[3])
        : "r"(a[0]), "r"(a[1]), "r"(a[2]), "r"(a[3]), "r"(b[0]), "r"(b[1]));
}
__device__ __forceinline__ float tanh_fast(float x) {
    float r;
    asm("tanh.approx.f32 %0, %1;" : "=f"(r) : "f"(x));
    return r;
}

// =====================================================================
// K0: W1 [k][n] fp32 -> g_W1Tb [n][k] bf16
// =====================================================================
__global__ void convW1_kernel(const float* __restrict__ W1) {
    __shared__ float t[32][33];
    int bx = blockIdx.x * 32, by = blockIdx.y * 32;
    t[threadIdx.y][threadIdx.x] = W1[(by + threadIdx.y) * UNITS + bx + threadIdx.x];
    __syncthreads();
    g_W1Tb[(size_t)(bx + threadIdx.y) * ENC + by + threadIdx.x] =
        __float2bfloat16(t[threadIdx.x][threadIdx.y]);
}

// =====================================================================
// K1: all small GEMM partials in one launch.
//  z=0: g_hidP = s_t_m @ W2   (c < 512)
//  z=1: g_gxP  = h_t   @ gWx  (c < 1536)
//  z=2: g_ghP  = s0    @ gWh  (c < 1536)
// =====================================================================
__global__ void gemm64_all_kernel(const float* __restrict__ s_t_m,
                                  const float* __restrict__ W2,
                                  const float* __restrict__ h_t,
                                  const float* __restrict__ gWx,
                                  const float* __restrict__ s0,
                                  const float* __restrict__ gWh) {
    const int z = blockIdx.z;
    if (z == 0 && blockIdx.x >= 4) return;
    const float* In; const float* W; float* outP; int ldW;
    if (z == 0)      { In = s_t_m; W = W2;  ldW = UNITS;     outP = g_hidP; }
    else if (z == 1) { In = h_t;   W = gWx; ldW = 3 * UNITS; outP = g_gxP; }
    else             { In = s0;    W = gWh; ldW = 3 * UNITS; outP = g_ghP; }

    const int c0 = blockIdx.x * 128;
    const int kz = blockIdx.y;
    const int tid = threadIdx.x, tc = tid & 127, bh = tid >> 7;
    __shared__ float xs[64][8];
    __shared__ float Ws[8][128];
    float acc[32];
    #pragma unroll
    for (int i = 0; i < 32; i++) acc[i] = 0.f;

    const int kbeg = kz * 64;
    for (int k0 = kbeg; k0 < kbeg + 64; k0 += 8) {
        #pragma unroll
        for (int j = 0; j < 2; j++) {
            int e = tid + j * 256;
            xs[e >> 3][e & 7] = In[(e >> 3) * UNITS + k0 + (e & 7)];
        }
        #pragma unroll
        for (int j = 0; j < 4; j++) {
            int e = tid + j * 256;
            Ws[e >> 7][e & 127] = W[(size_t)(k0 + (e >> 7)) * ldW + c0 + (e & 127)];
        }
        __syncthreads();
        #pragma unroll
        for (int kk = 0; kk < 8; kk++) {
            float wv = Ws[kk][tc];
            #pragma unroll
            for (int bb = 0; bb < 32; bb++) acc[bb] += xs[bh * 32 + bb][kk] * wv;
        }
        __syncthreads();
    }
    #pragma unroll
    for (int bb = 0; bb < 32; bb++)
        outP[((size_t)kz * BATCH + bh * 32 + bb) * ldW + c0 + tc] = acc[bb];
}

// fold W2b into hidden partial p=0 (robust to nonzero W2_b)
__global__ void addW2b_kernel(const float* __restrict__ W2b) {
    int b = blockIdx.x, u = threadIdx.x;
    g_hidP[(size_t)b * UNITS + u] += W2b[u];
}

// =====================================================================
// K2: bf16 mma.sync + ldmatrix score GEMM with in-kernel fp32->bf16
// A-staging (LDG->regs during MMA, cvt+STS after). Block 128(T)x256(N),
// K chunk 64, one __syncthreads per stage.
//   scoreP[b,ny,t] = sum_{n in half} V[n]*tanh(H@W1 + W1b[n] + hid[b,n])
// =====================================================================
#define SM_A(buf) ((uint32_t)(buf) * 16384u)
#define SM_B(buf) (32768u + (uint32_t)(buf) * 32768u)
#define SMEM_SCORE_BYTES 102400

__global__ void __launch_bounds__(256, 1)
score_kernel(const float* __restrict__ H, const float* __restrict__ W1b,
             const float* __restrict__ Vw) {
    extern __shared__ uint32_t dyn[];
    float* sbias = (float*)(dyn + 24576);   // 256 f
    float* sV    = sbias + 256;             // 256 f
    float* red   = sV + 256;                // 512 f

    const int tid = threadIdx.x;
    const int w = tid >> 5, lane = tid & 31;
    const int g = lane >> 2, tig = lane & 3;
    const int warpM = w & 1, warpN = w >> 1;
    const int b = blockIdx.z, t0 = blockIdx.x * 128, n0 = blockIdx.y * 256;
    const uint32_t sbase = smem_u32(dyn);

    {   // bias = W1b + sum_p hidden partials (hidden_combine fused)
        float a = W1b[n0 + tid];
        #pragma unroll
        for (int p = 0; p < 8; p++)
            a += g_hidP[((size_t)p * BATCH + b) * UNITS + n0 + tid];
        sbias[tid] = a;
        sV[tid]    = Vw[n0 + tid];
    }

    const float* Af = H + ((size_t)b * TT + t0) * ENC;         // fp32 A
    const __nv_bfloat16* Bg = g_W1Tb + (size_t)n0 * ENC;       // bf16 B

    float4 rA[8];   // 4 segments x 2 float4 (chunk staged in regs)
    auto ldgA = [&](int k0) {
        #pragma unroll
        for (int j = 0; j < 4; j++) {
            int i = tid + j * 256, r = i >> 3, sg = i & 7;
            const float4* src = (const float4*)(Af + (size_t)r * ENC + k0 + sg * 8);
            rA[j * 2]     = src[0];
            rA[j * 2 + 1] = src[1];
        }
    };
    auto stsA = [&](int buf) {
        #pragma unroll
        for (int j = 0; j < 4; j++) {
            int i = tid + j * 256, r = i >> 3, sg = i & 7;
            uint32_t off = SM_A(buf) + (uint32_t)r * 128u
                         + (uint32_t)((sg ^ (r & 7)) << 4);
            __nv_bfloat162 c0 = __floats2bfloat162_rn(rA[j*2].x,   rA[j*2].y);
            __nv_bfloat162 c1 = __floats2bfloat162_rn(rA[j*2].z,   rA[j*2].w);
            __nv_bfloat162 c2 = __floats2bfloat162_rn(rA[j*2+1].x, rA[j*2+1].y);
            __nv_bfloat162 c3 = __floats2bfloat162_rn(rA[j*2+1].z, rA[j*2+1].w);
            uint4 v;
            v.x = *(uint32_t*)&c0; v.y = *(uint32_t*)&c1;
            v.z = *(uint32_t*)&c2; v.w = *(uint32_t*)&c3;
            *(uint4*)((char*)dyn + off) = v;
        }
    };
    auto loadB = [&](int buf, int k0) {
        #pragma unroll
        for (int j = 0; j < 8; j++) {
            int e = tid + j * 256, r = e >> 3, s = e & 7;
            uint32_t off = SM_B(buf) + (uint32_t)r * 128u
                         + (uint32_t)((s ^ (r & 7)) << 4);
            CP16(sbase + off, Bg + (size_t)r * ENC + k0 + s * 8);
        }
    };

    uint32_t aOff[4], aRs[4], bOff[4], bRs[4];
    const uint32_t aHi = (lane >> 4) & 1;
    const uint32_t bHi = (lane >> 3) & 1;
    #pragma unroll
    for (int mt = 0; mt < 4; mt++) {
        int row = warpM * 64 + mt * 16 + (lane & 15);
        aOff[mt] = (uint32_t)row * 128u;
        aRs[mt]  = (uint32_t)(row & 7);
    }
    #pragma unroll
    for (int pr = 0; pr < 4; pr++) {
        int n = warpN * 64 + pr * 16 + (lane & 7) + ((lane >> 4) << 3);
        bOff[pr] = (uint32_t)n * 128u;
        bRs[pr]  = (uint32_t)(n & 7);
    }

    float acc[4][8][4];
    #pragma unroll
    for (int mt = 0; mt < 4; mt++)
        #pragma unroll
        for (int nt = 0; nt < 8; nt++)
            #pragma unroll
            for (int q = 0; q < 4; q++) acc[mt][nt][q] = 0.f;

    ldgA(0);
    loadB(0, 0);
    CP_COMMIT();
    stsA(0);

    const int NS = ENC / 64;   // 8 stages
    for (int s = 0; s < NS; s++) {
        if (s < NS - 1) {
            ldgA((s + 1) * 64);
            loadB((s + 1) & 1, (s + 1) * 64);
            CP_COMMIT();
            CP_WAIT1();
        } else {
            CP_WAIT0();
        }
        __syncthreads();
        const int cur = s & 1;

        #pragma unroll
        for (int kk = 0; kk < 4; kk++) {
            uint32_t af[4][4], bq[4][4];
            #pragma unroll
            for (int mt = 0; mt < 4; mt++) {
                uint32_t addr = sbase + SM_A(cur) + aOff[mt]
                              + (((((uint32_t)kk << 1) | aHi) ^ aRs[mt]) << 4);
                LDSM4(af[mt][0], af[mt][1], af[mt][2], af[mt][3], addr);
            }
            #pragma unroll
            for (int pr = 0; pr < 4; pr++) {
                uint32_t addr = sbase + SM_B(cur) + bOff[pr]
                              + (((((uint32_t)kk << 1) | bHi) ^ bRs[pr]) << 4);
                LDSM4(bq[pr][0], bq[pr][1], bq[pr][2], bq[pr][3], addr);
            }
            #pragma unroll
            for (int mt = 0; mt < 4; mt++)
                #pragma unroll
                for (int pr = 0; pr < 4; pr++) {
                    mma_bf16(acc[mt][pr * 2],     af[mt], &bq[pr][0]);
                    mma_bf16(acc[mt][pr * 2 + 1], af[mt], &bq[pr][2]);
                }
        }
        if (s < NS - 1) stsA((s + 1) & 1);
    }

    float pa[4], pb[4];
    #pragma unroll
    for (int mt = 0; mt < 4; mt++) { pa[mt] = 0.f; pb[mt] = 0.f; }
    #pragma unroll
    for (int nt = 0; nt < 8; nt++) {
        int nn = warpN * 64 + nt * 8 + 2 * tig;
        float s0 = sbias[nn], s1 = sbias[nn + 1];
        float v0 = sV[nn],    v1 = sV[nn + 1];
        #pragma unroll
        for (int mt = 0; mt < 4; mt++) {
            pa[mt] += v0 * tanh_fast(acc[mt][nt][0] + s0) + v1 * tanh_fast(acc[mt][nt][1] + s1);
            pb[mt] += v0 * tanh_fast(acc[mt][nt][2] + s0) + v1 * tanh_fast(acc[mt][nt][3] + s1);
        }
    }
    #pragma unroll
    for (int mt = 0; mt < 4; mt++) {
        pa[mt] += __shfl_xor_sync(0xffffffffu, pa[mt], 1);
        pa[mt] += __shfl_xor_sync(0xffffffffu, pa[mt], 2);
        pb[mt] += __shfl_xor_sync(0xffffffffu, pb[mt], 1);
        pb[mt] += __shfl_xor_sync(0xffffffffu, pb[mt], 2);
    }
    if (tig == 0) {
        #pragma unroll
        for (int mt = 0; mt < 4; mt++) {
            int r = warpM * 64 + mt * 16 + g;
            red[warpN * 128 + r]     = pa[mt];
            red[warpN * 128 + r + 8] = pb[mt];
        }
    }
    __syncthreads();
    if (tid < 128) {
        float s = red[tid] + red[128 + tid] + red[256 + tid] + red[384 + tid];
        g_scoreP[((size_t)b * 2 + blockIdx.y) * TT + t0 + tid] = s;
    }
}

// =====================================================================
// K3: softmax over T per batch (V_b constant -> cancels)
// =====================================================================
__global__ void softmax_kernel() {
    int b = blockIdx.x, tid = threadIdx.x;
    __shared__ float red[256];
    float sv[8];
    float mx = -1e30f;
    #pragma unroll
    for (int i = 0; i < 8; i++) {
        int t = tid + i * 256;
        sv[i] = g_scoreP[(size_t)b * 2 * TT + t] + g_scoreP[((size_t)b * 2 + 1) * TT + t];
        mx = fmaxf(mx, sv[i]);
    }
    red[tid] = mx; __syncthreads();
    for (int o = 128; o > 0; o >>= 1) {
        if (tid < o) red[tid] = fmaxf(red[tid], red[tid + o]);
        __syncthreads();
    }
    mx = red[0]; __syncthreads();
    float sum = 0.f;
    #pragma unroll
    for (int i = 0; i < 8; i++) { sv[i] = expf(sv[i] - mx); sum += sv[i]; }
    red[tid] = sum; __syncthreads();
    for (int o = 128; o > 0; o >>= 1) {
        if (tid < o) red[tid] += red[tid + o];
        __syncthreads();
    }
    float inv = 1.f / red[0];
    #pragma unroll
    for (int i = 0; i < 8; i++) g_w[b * TT + tid + i * 256] = sv[i] * inv;
}

// =====================================================================
// K4: context partials from fp32 H (float2 vectorized)
// =====================================================================
__global__ void context_kernel(const float* __restrict__ H) {
    int b = blockIdx.y, ch = blockIdx.x, tid = threadIdx.x;
    const int TC = TT / TCH;
    __shared__ float ws[TC];
    int tBeg = ch * TC;
    for (int i = tid; i < TC; i += 256) ws[i] = g_w[b * TT + tBeg + i];
    __syncthreads();
    float ax = 0.f, ay = 0.f;
    const float2* Hb = (const float2*)(H + ((size_t)b * TT + tBeg) * ENC) + tid;
    #pragma unroll 4
    for (int t = 0; t < TC; t++) {
        float2 v = Hb[(size_t)t * (ENC / 2)];
        ax += ws[t] * v.x;
        ay += ws[t] * v.y;
    }
    float* dst = g_ctxP + ((size_t)b * TCH + ch) * ENC + 2 * tid;
    dst[0] = ax; dst[1] = ay;
}

// =====================================================================
// K5: GRU combine + gated fusion + vocab projection (one launch)
// =====================================================================
__global__ void fusion_kernel(const float* __restrict__ s0,
                              const float* __restrict__ gbi, const float* __restrict__ gbr,
                              const float* __restrict__ Wfa, const float* __restrict__ Wfab,
                              const float* __restrict__ Wff, const float* __restrict__ Wffb,
                              const float* __restrict__ Wfh, const float* __restrict__ Wfhb,
                              const float* __restrict__ Wy,  const float* __restrict__ Wyb,
                              float* __restrict__ s_out, float* __restrict__ y_out) {
    __shared__ float ctx[ENC], pc[UNITS], st[UNITS], ft[UNITS], yred[512];
    int b = blockIdx.x, u = threadIdx.x;

    {   // GRU combine (Keras reset_after=True; gate order z,r,h)
        float xz = gbi[u], xr = gbi[UNITS + u], xh = gbi[2 * UNITS + u];
        float hz = gbr[u], hr = gbr[UNITS + u], hh = gbr[2 * UNITS + u];
        #pragma unroll
        for (int p = 0; p < 8; p++) {
            const float* X  = g_gxP + ((size_t)p * BATCH + b) * (3 * UNITS);
            const float* Hg = g_ghP + ((size_t)p * BATCH + b) * (3 * UNITS);
            xz += X[u];  xr += X[UNITS + u];  xh += X[2 * UNITS + u];
            hz += Hg[u]; hr += Hg[UNITS + u]; hh += Hg[2 * UNITS + u];
        }
        float hprev = s0[b * UNITS + u];
        float z  = 1.f / (1.f + expf(-(xz + hz)));
        float r  = 1.f / (1.f + expf(-(xr + hr)));
        float hc = tanhf(xh + r * hh);
        float sv = z * hprev + (1.f - z) * hc;
        s_out[b * UNITS + u] = sv;
        st[u] = sv;
    }

    float c = 0.f;
    #pragma unroll
    for (int ch = 0; ch < TCH; ch++) c += g_ctxP[((size_t)b * TCH + ch) * ENC + u];
    ctx[u] = c;
    __syncthreads();

    float p = Wfab[u];
    #pragma unroll 4
    for (int k = 0; k < ENC; k++) p += ctx[k] * Wfa[(size_t)k * UNITS + u];
    pc[u] = p;
    __syncthreads();

    float fw = Wffb[u] + Wfhb[u];
    #pragma unroll 4
    for (int k = 0; k < UNITS; k++)
        fw += pc[k] * Wff[(size_t)k * UNITS + u] + st[k] * Wfh[(size_t)k * UNITS + u];
    fw = 1.f / (1.f + expf(-fw));
    ft[u] = pc[u] * fw + st[u];
    __syncthreads();

    int v = u & 31, part = u >> 5;
    float acc = 0.f;
    for (int k = part; k < UNITS; k += 16) acc += ft[k] * Wy[(size_t)k * VOCAB + v];
    yred[u] = acc;
    __syncthreads();
    if (part == 0) {
        float s = Wyb[v];
        #pragma unroll
        for (int pp = 0; pp < 16; pp++) s += yred[pp * 32 + v];
        y_out[b * VOCAB + v] = s;
    }
}

// =====================================================================
extern "C" void kernel_launch(void* const* d_in, const int* in_sizes, int n_in,
                              void* d_out, int out_size) {
    const float* h_t   = (const float*)d_in[0];
    const float* s_t_m = (const float*)d_in[1];
    const float* H     = (const float*)d_in[2];
    const float* s0    = (const float*)d_in[3];
    const float* W1w   = (const float*)d_in[4];
    const float* W1b   = (const float*)d_in[5];
    const float* W2w   = (const float*)d_in[6];
    const float* W2b   = (const float*)d_in[7];
    const float* Vw    = (const float*)d_in[8];
    // d_in[9] = V_b: constant over t, cancels in softmax
    const float* gWx   = (const float*)d_in[10];
    const float* gWh   = (const float*)d_in[11];
    const float* gbi   = (const float*)d_in[12];
    const float* gbr   = (const float*)d_in[13];
    const float* Wfa   = (const float*)d_in[14];
    const float* Wfab  = (const float*)d_in[15];
    const float* Wff   = (const float*)d_in[16];
    const float* Wffb  = (const float*)d_in[17];
    const float* Wfh   = (const float*)d_in[18];
    const float* Wfhb  = (const float*)d_in[19];
    const float* Wy    = (const float*)d_in[20];
    const float* Wyb   = (const float*)d_in[21];

    float* out   = (float*)d_out;
    float* y_out = out;                       // y_t: [64, 32]
    float* s_out = out + BATCH * VOCAB;       // s_t: [64, 512]

    cudaFuncSetAttribute(score_kernel,
                         cudaFuncAttributeMaxDynamicSharedMemorySize, SMEM_SCORE_BYTES);

    convW1_kernel<<<dim3(16, 16), dim3(32, 32)>>>(W1w);
    gemm64_all_kernel<<<dim3(12, 8, 3), 256>>>(s_t_m, W2w, h_t, gWx, s0, gWh);
    addW2b_kernel<<<BATCH, UNITS>>>(W2b);
    score_kernel<<<dim3(TT / 128, 2, BATCH), 256, SMEM_SCORE_BYTES>>>(H, W1b, Vw);
    softmax_kernel<<<BATCH, 256>>>();
    context_kernel<<<dim3(TCH, BATCH), 256>>>(H);
    fusion_kernel<<<BATCH, UNITS>>>(s0, gbi, gbr, Wfa, Wfab, Wff, Wffb,
                                    Wfh, Wfhb, Wy, Wyb, s_out, y_out);
}